// round 16
// baseline (speedup 1.0000x reference)
#include <cuda_runtime.h>

// ---------------- problem constants ----------------
#define T_STEPS 300
#define NB 4
#define MSL 1200            // T_STEPS * NB time-batch slices

#define A_SR 0.90483741803595952f   // exp(-1/10)
#define A_RF 0.36787944117144233f   // exp(-1)
#define C_SR 0.27182818284590452f   // e/10
#define C_RF -54.365636569180904f   // -2*theta*e
#define THETA 10.0f

// ---------------- packed f32x2 helpers (Blackwell 2xFP32) ----------------
__device__ __forceinline__ unsigned long long ffma2(unsigned long long a,
                                                    unsigned long long b,
                                                    unsigned long long c) {
    unsigned long long d;
    asm("fma.rn.f32x2 %0, %1, %2, %3;" : "=l"(d) : "l"(a), "l"(b), "l"(c));
    return d;
}
__device__ __forceinline__ unsigned long long addf2(unsigned long long a,
                                                    unsigned long long b) {
    unsigned long long d;
    asm("add.rn.f32x2 %0, %1, %2;" : "=l"(d) : "l"(a), "l"(b));
    return d;
}
__device__ __forceinline__ unsigned long long pack2(float lo, float hi) {
    unsigned long long d;
    asm("mov.b64 %0, {%1, %2};" : "=l"(d) : "f"(lo), "f"(hi));
    return d;
}
__device__ __forceinline__ float2 unpack2(unsigned long long d) {
    float2 r;
    asm("mov.b64 {%0, %1}, %2;" : "=f"(r.x), "=f"(r.y) : "l"(d));
    return r;
}

__device__ __forceinline__ float f4c(const float4& v, int k) {
    switch (k) {
        case 0: return v.x;
        case 1: return v.y;
        case 2: return v.z;
        default: return v.w;
    }
}

// ---------------- scratch buffers (time-major [t][n][c][h][w]) ----------------
__device__ float g_buf1[2457600];   // pooled1 spikes: [1200][2][32][32]
__device__ float g_buf3[9830400];   // pooled spikes : [1200][32][16][16]
__device__ float g_buf4[19660800];  // conv2 raw     : [1200][64][16][16]
__device__ float g_buf5[4915200];   // pooled spikes : [1200][64][8][8]
__device__ float g_buf6[4915200];   // conv3 raw/spk : [1200][64][8][8]
__device__ float g_buf7[307200];    // fc1           : [1200][256]
__device__ float g_buf8[13200];     // fc2           : [1200][11]
__device__ float g_w2t[18432];      // w2 transposed [ci32][tap9][co64]
__device__ float g_w3t[36864];      // w3 transposed [ci64][tap9][co64]

// ---------------- one-shot weight transposes ----------------
__global__ void k_wt2(const float* __restrict__ w, float* __restrict__ o) {
    int i = blockIdx.x * blockDim.x + threadIdx.x;
    if (i >= 18432) return;
    int co = i & 63, tap = (i >> 6) % 9, ci = i / 576;
    o[i] = w[co * 288 + ci * 9 + tap];
}
__global__ void k_wt3(const float* __restrict__ w, float* __restrict__ o) {
    int i = blockIdx.x * blockDim.x + threadIdx.x;
    if (i >= 36864) return;
    int co = i & 63, tap = (i >> 6) % 9, ci = i / 576;
    o[i] = w[co * 576 + ci * 9 + tap];
}

// ---------------- fused 4x4 pool + psp, 4 threads per pooled neuron -----------
__global__ void k_pool4psp(const float* __restrict__ s_in, float* __restrict__ y) {
    int j = blockIdx.x * blockDim.x + threadIdx.x;
    if (j >= 32768) return;
    int neuron = j >> 2, q = j & 3;
    int w = neuron & 31, h = (neuron >> 5) & 31, c = (neuron >> 10) & 1, n = neuron >> 11;
    const float* src = s_in + (((n * 2 + c) * 128 + h * 4 + q) * 128 + w * 4) * 300;

    float4 cur[4], nxt[4];
#pragma unroll
    for (int dj = 0; dj < 4; dj++) cur[dj] = *(const float4*)(src + dj * 300);

    float gp = 0.f, hp = 0.f, gr = 0.f, hr = 0.f;

    for (int ch = 0; ch < 75; ch++) {
        if (ch < 74) {
            const float* p = src + 4 * (ch + 1);
#pragma unroll
            for (int dj = 0; dj < 4; dj++) nxt[dj] = *(const float4*)(p + dj * 300);
        }
#pragma unroll
        for (int k = 0; k < 4; k++) {
            int t = 4 * ch + k;
            float mysum = f4c(cur[0], k) + f4c(cur[1], k) + f4c(cur[2], k) + f4c(cur[3], k);
            mysum += __shfl_xor_sync(0xffffffffu, mysum, 1);
            mysum += __shfl_xor_sync(0xffffffffu, mysum, 2);
            float pv = 11.0f * mysum;
            hp = A_SR * (hp + gp);
            gp = fmaf(A_SR, gp, pv);
            hr = A_RF * (hr + gr);
            gr = A_RF * gr;
            float u = fmaf(C_SR, hp, C_RF * hr);
            float s = (u >= THETA) ? 1.0f : 0.0f;
            gr += s;
            if (q == 0) y[t * 8192 + neuron] = s;
        }
#pragma unroll
        for (int dj = 0; dj < 4; dj++) cur[dj] = nxt[dj];
    }
}

// ---------------- psp + spike, in-place, depth-4 prefetch ring ----------------
__global__ void k_psp(float* __restrict__ x, int nn) {
    int j = blockIdx.x * blockDim.x + threadIdx.x;
    if (j >= nn) return;
    float buf[4];
#pragma unroll
    for (int t = 0; t < 4; t++) buf[t] = x[t * nn + j];
    float gp = 0.f, hp = 0.f, gr = 0.f, hr = 0.f;
    for (int t = 0; t < T_STEPS; t++) {
        int slot = t & 3;
        float v = buf[slot];
        if (t + 4 < T_STEPS) buf[slot] = x[(t + 4) * nn + j];
        hp = A_SR * (hp + gp);
        gp = fmaf(A_SR, gp, v);
        hr = A_RF * (hr + gr);
        gr = A_RF * gr;
        float u = fmaf(C_SR, hp, C_RF * hr);
        float s = (u >= THETA) ? 1.0f : 0.0f;
        x[t * nn + j] = s;
        gr += s;
    }
}

// final psp: reads [t][44], depth-4 prefetch, writes d_out in (N,11,T) layout
__global__ void k_psp_final(const float* __restrict__ x, float* __restrict__ out) {
    int j = threadIdx.x;
    if (j >= 44) return;
    float buf[4];
#pragma unroll
    for (int t = 0; t < 4; t++) buf[t] = x[t * 44 + j];
    float gp = 0.f, hp = 0.f, gr = 0.f, hr = 0.f;
    for (int t = 0; t < T_STEPS; t++) {
        int slot = t & 3;
        float v = buf[slot];
        if (t + 4 < T_STEPS) buf[slot] = x[(t + 4) * 44 + j];
        hp = A_SR * (hp + gp);
        gp = fmaf(A_SR, gp, v);
        hr = A_RF * (hr + gr);
        gr = A_RF * gr;
        float u = fmaf(C_SR, hp, C_RF * hr);
        float s = (u >= THETA) ? 1.0f : 0.0f;
        out[j * T_STEPS + t] = s;
        gr += s;
    }
}

// ---------------- persistent fused conv1 + psp + 2x2 pool + psp ----------------
#define C1_SLICE 1296               // 36*36
#define C1_TBUF (2 * C1_SLICE)      // one t: 2 ci planes
__global__ void __launch_bounds__(256, 1)
k_conv1f(const float* __restrict__ x, const float* __restrict__ w,
         float* __restrict__ y) {
    extern __shared__ float sm[];   // [buf2][tt4][ci2][36][36]
    int n = blockIdx.x, co = blockIdx.y;
    int tid = threadIdx.x;
    int pw = tid & 15, ph = tid >> 4;

    for (int i = tid; i < 2 * 4 * C1_TBUF; i += 256) sm[i] = 0.f;

    float wr[50];
#pragma unroll
    for (int i = 0; i < 50; i++) wr[i] = w[co * 50 + i];

    __syncthreads();
    const float* xb = x + n * 2048;
    const int TSTR = 8192;          // floats per t in b1: 4n * 2048

#pragma unroll
    for (int tt = 0; tt < 4; tt++) {
        const float* xp = xb + tt * TSTR;
#pragma unroll
        for (int k = 0; k < 2; k++) {
            int idx = tid + k * 256;
            float4 f = ((const float4*)xp)[idx];
            int lin = idx * 4;
            int ci = lin >> 10, r = lin & 1023, h = r >> 5, ww = r & 31;
            float* dst = sm + tt * C1_TBUF + ci * C1_SLICE + (h + 2) * 36 + (ww + 2);
            dst[0] = f.x; dst[1] = f.y; dst[2] = f.z; dst[3] = f.w;
        }
    }
    __syncthreads();

    float gp[4] = {0, 0, 0, 0}, hp[4] = {0, 0, 0, 0};
    float gr[4] = {0, 0, 0, 0}, hr[4] = {0, 0, 0, 0};
    float gpp = 0.f, hpp = 0.f, grp = 0.f, hrp = 0.f;

    for (int c = 0; c < 75; c++) {
        int cb = c & 1;
        float* cbuf = sm + cb * 4 * C1_TBUF;
        if (c < 74) {
            float* nbuf = sm + (cb ^ 1) * 4 * C1_TBUF;
#pragma unroll
            for (int tt = 0; tt < 4; tt++) {
                const float* xp = xb + (4 * (c + 1) + tt) * TSTR;
#pragma unroll
                for (int k = 0; k < 2; k++) {
                    int idx = tid + k * 256;
                    float4 f = ((const float4*)xp)[idx];
                    int lin = idx * 4;
                    int ci = lin >> 10, r = lin & 1023, h = r >> 5, ww = r & 31;
                    float* dst = nbuf + tt * C1_TBUF + ci * C1_SLICE + (h + 2) * 36 + (ww + 2);
                    dst[0] = f.x; dst[1] = f.y; dst[2] = f.z; dst[3] = f.w;
                }
            }
        }
#pragma unroll
        for (int tt = 0; tt < 4; tt++) {
            int t = 4 * c + tt;
            const float* tb = cbuf + tt * C1_TBUF;
            unsigned long long a0 = 0ull, a1 = 0ull;
#pragma unroll
            for (int ci = 0; ci < 2; ci++) {
                const float* pb = tb + ci * C1_SLICE;
                float p[6][6];
#pragma unroll
                for (int r = 0; r < 6; r++) {
#pragma unroll
                    for (int cpair = 0; cpair < 3; cpair++) {
                        float2 v = *(const float2*)(pb + (2 * ph + r) * 36 + 2 * pw + 2 * cpair);
                        p[r][2 * cpair] = v.x;
                        p[r][2 * cpair + 1] = v.y;
                    }
                }
#pragma unroll
                for (int kh = 0; kh < 5; kh++)
#pragma unroll
                    for (int kw = 0; kw < 5; kw++) {
                        float wv = wr[ci * 25 + kh * 5 + kw];
                        unsigned long long ws = pack2(wv, wv);
                        a0 = ffma2(pack2(p[kh][kw], p[kh][kw + 1]), ws, a0);
                        a1 = ffma2(pack2(p[kh + 1][kw], p[kh + 1][kw + 1]), ws, a1);
                    }
            }
            float2 f0 = unpack2(a0), f1 = unpack2(a1);
            float av[4] = {f0.x, f0.y, f1.x, f1.y};
            float psum = 0.f;
#pragma unroll
            for (int k = 0; k < 4; k++) {
                hp[k] = A_SR * (hp[k] + gp[k]);
                gp[k] = fmaf(A_SR, gp[k], av[k]);
                hr[k] = A_RF * (hr[k] + gr[k]);
                gr[k] = A_RF * gr[k];
                float u = fmaf(C_SR, hp[k], C_RF * hr[k]);
                float s = (u >= THETA) ? 1.0f : 0.0f;
                gr[k] += s;
                psum += s;
            }
            float pv = 11.0f * psum;
            hpp = A_SR * (hpp + gpp);
            gpp = fmaf(A_SR, gpp, pv);
            hrp = A_RF * (hrp + grp);
            grp = A_RF * grp;
            float u = fmaf(C_SR, hpp, C_RF * hrp);
            float s = (u >= THETA) ? 1.0f : 0.0f;
            grp += s;
            y[t * 32768 + ((n * 32 + co) * 16 + ph) * 16 + pw] = s;
        }
        __syncthreads();
    }
}

// ---------------- fused psp -> 2x2 pool -> psp, 4 threads per pooled neuron ----
template <int C, int HO, int WO>
__global__ void k_ppp4(const float* __restrict__ x, float* __restrict__ y) {
    const int NN = 4 * C * HO * WO;
    const int WI = 2 * WO;
    const int STRIDE = 4 * C * (2 * HO) * WI;
    int j = blockIdx.x * blockDim.x + threadIdx.x;
    if (j >= 4 * NN) return;
    int neuron = j >> 2, q = j & 3;
    int wo = neuron % WO, ho = (neuron / WO) % HO;
    int c = (neuron / (WO * HO)) % C, n = neuron / (WO * HO * C);
    const float* src = x + (((n * C + c) * (2 * HO) + 2 * ho + (q >> 1)) * WI) +
                       2 * wo + (q & 1);

    float buf[4];
#pragma unroll
    for (int t = 0; t < 4; t++) buf[t] = src[t * STRIDE];

    float gp = 0.f, hp = 0.f, gr = 0.f, hr = 0.f;
    float gpp = 0.f, hpp = 0.f, grp = 0.f, hrp = 0.f;

    for (int t = 0; t < T_STEPS; t++) {
        int slot = t & 3;
        float v = buf[slot];
        if (t + 4 < T_STEPS) buf[slot] = src[(t + 4) * STRIDE];
        hp = A_SR * (hp + gp);
        gp = fmaf(A_SR, gp, v);
        hr = A_RF * (hr + gr);
        gr = A_RF * gr;
        float u = fmaf(C_SR, hp, C_RF * hr);
        float s = (u >= THETA) ? 1.0f : 0.0f;
        gr += s;
        s += __shfl_xor_sync(0xffffffffu, s, 1);
        s += __shfl_xor_sync(0xffffffffu, s, 2);
        float pv = 11.0f * s;
        hpp = A_SR * (hpp + gpp);
        gpp = fmaf(A_SR, gpp, pv);
        hrp = A_RF * (hrp + grp);
        grp = A_RF * grp;
        float up = fmaf(C_SR, hpp, C_RF * hrp);
        float sp = (up >= THETA) ? 1.0f : 0.0f;
        grp += sp;
        if (q == 0) y[t * NN + neuron] = sp;
    }
}

// ---------------- conv2: 3x3, 32->64, 16x16, pad 1 -----------------------------
// Density-adaptive: per-pixel 32-bit ci spike masks built from global; if block
// density < 1/3 use sparse bit-iteration (weights add directly, spike==1.0),
// else fall back to the dense f32x2 path. Summation order differs dense/sparse
// (ci-outer vs tap-outer); skipped zeros are exact in both.
__global__ void k_conv2(const float* __restrict__ x, const float* __restrict__ wt,
                        float* __restrict__ y) {
    extern __shared__ float sm[];
    float* in_s = sm;                         // 32*18*18 = 10368 (dense path only)
    float* w_s = sm + 10368;                  // [ci][tap][32co] = 9216
    unsigned* msk = (unsigned*)(sm + 19584);  // 18*18 = 324 pixel masks
    int* cnt = (int*)(sm + 19908);
    int mIdx = blockIdx.x;
    int cog = blockIdx.y;
    int tid = threadIdx.x;

    for (int i = tid; i < 324; i += 256) msk[i] = 0;
    if (tid == 0) *cnt = 0;
    for (int i = tid; i < 9216; i += 256)
        w_s[i] = wt[(i >> 5) * 64 + cog * 32 + (i & 31)];
    __syncthreads();

    // build interior masks straight from global (coalesced: pixel = tid)
    const float* xb = x + mIdx * 8192;
    {
        int h = tid >> 4, ww = tid & 15;
        unsigned m = 0;
#pragma unroll
        for (int ci = 0; ci < 32; ci++)
            if (xb[ci * 256 + tid] != 0.f) m |= 1u << ci;
        msk[(h + 1) * 18 + ww + 1] = m;
        int c = __popc(m);
#pragma unroll
        for (int s = 16; s; s >>= 1) c += __shfl_xor_sync(0xffffffffu, c, s);
        if ((tid & 31) == 0) atomicAdd(cnt, c);
    }
    __syncthreads();
    int total = *cnt;

    int wx = tid & 15, g = (tid >> 4) & 3, ty = tid >> 6;
    unsigned long long acc2[4][4];
#pragma unroll
    for (int p = 0; p < 4; p++)
#pragma unroll
        for (int jj = 0; jj < 4; jj++) acc2[p][jj] = 0ull;

    if (total * 3 < 8192) {
        // ---- sparse: iterate set ci bits per (position, tap) ----
#pragma unroll
        for (int p = 0; p < 4; p++) {
            int row0 = ty + 4 * p;
#pragma unroll
            for (int kh = 0; kh < 3; kh++)
#pragma unroll
                for (int kw = 0; kw < 3; kw++) {
                    unsigned m = msk[(row0 + kh) * 18 + wx + kw];
                    const float* wt0 = w_s + (kh * 3 + kw) * 32 + g * 8;
                    while (m) {
                        int ci = __ffs(m) - 1;
                        m &= m - 1;
                        const float* wp = wt0 + ci * 288;
                        ulonglong2 wa = *(const ulonglong2*)wp;
                        ulonglong2 wb = *(const ulonglong2*)(wp + 4);
                        acc2[p][0] = addf2(acc2[p][0], wa.x);
                        acc2[p][1] = addf2(acc2[p][1], wa.y);
                        acc2[p][2] = addf2(acc2[p][2], wb.x);
                        acc2[p][3] = addf2(acc2[p][3], wb.y);
                    }
                }
        }
    } else {
        // ---- dense fallback (original path) ----
        for (int i = tid; i < 10368; i += 256) in_s[i] = 0.f;
        __syncthreads();
        for (int i = tid; i < 8192; i += 256) {
            int ci = i >> 8, r = i & 255, h = r >> 4, ww = r & 15;
            in_s[ci * 324 + (h + 1) * 18 + (ww + 1)] = xb[i];
        }
        __syncthreads();
        for (int ci = 0; ci < 32; ci++) {
            const float* ip = in_s + ci * 324 + wx;
            const float* wp = w_s + ci * 288 + g * 8;
#pragma unroll
            for (int kh = 0; kh < 3; kh++)
#pragma unroll
                for (int kw = 0; kw < 3; kw++) {
                    int tap = kh * 3 + kw;
                    ulonglong2 wa = *(const ulonglong2*)(wp + tap * 32);
                    ulonglong2 wb = *(const ulonglong2*)(wp + tap * 32 + 4);
                    unsigned long long wv2[4] = {wa.x, wa.y, wb.x, wb.y};
#pragma unroll
                    for (int p = 0; p < 4; p++) {
                        float v = ip[(ty + 4 * p + kh) * 18 + kw];
                        unsigned long long vs = pack2(v, v);
#pragma unroll
                        for (int jj = 0; jj < 4; jj++)
                            acc2[p][jj] = ffma2(vs, wv2[jj], acc2[p][jj]);
                    }
                }
        }
    }

    float* yb = y + (mIdx * 64 + cog * 32 + g * 8) * 256;
#pragma unroll
    for (int p = 0; p < 4; p++) {
        int h = ty + 4 * p;
#pragma unroll
        for (int jj = 0; jj < 4; jj++) {
            float2 c = unpack2(acc2[p][jj]);
            yb[(2 * jj) * 256 + h * 16 + wx] = c.x;
            yb[(2 * jj + 1) * 256 + h * 16 + wx] = c.y;
        }
    }
}

// ---------------- conv3: 3x3, 64->64, 8x8, pad 1 -------------------------------
// Same density-adaptive scheme with 64-bit ci masks.
__global__ void k_conv3(const float* __restrict__ x, const float* __restrict__ wt,
                        float* __restrict__ y) {
    extern __shared__ float sm[];
    float* in_s = sm;                                      // 64*10*10 = 6400
    float* w_s = sm + 6400;                                // [ci64][tap][32co] = 18432
    unsigned long long* msk = (unsigned long long*)(sm + 24832);  // 10*10 masks
    int* cnt = (int*)(sm + 25032);
    int mIdx = blockIdx.x;
    int cog = blockIdx.y;
    int tid = threadIdx.x;

    for (int i = tid; i < 100; i += 256) msk[i] = 0ull;
    if (tid == 0) *cnt = 0;
    for (int i = tid; i < 18432; i += 256)
        w_s[i] = wt[(i >> 5) * 64 + cog * 32 + (i & 31)];
    __syncthreads();

    const float* xb = x + mIdx * 4096;
    if (tid < 64) {
        int h = tid >> 3, ww = tid & 7;
        unsigned long long m = 0ull;
#pragma unroll
        for (int ci = 0; ci < 64; ci++)
            if (xb[ci * 64 + tid] != 0.f) m |= 1ull << ci;
        msk[(h + 1) * 10 + ww + 1] = m;
        int c = __popcll(m);
#pragma unroll
        for (int s = 16; s; s >>= 1) c += __shfl_xor_sync(0xffffffffu, c, s);
        if ((tid & 31) == 0) atomicAdd(cnt, c);
    }
    __syncthreads();
    int total = *cnt;

    int wx = tid & 7, g = (tid >> 3) & 3, hy = tid >> 5;
    unsigned long long acc2[4] = {0ull, 0ull, 0ull, 0ull};

    if (total * 3 < 4096) {
        // ---- sparse ----
#pragma unroll
        for (int kh = 0; kh < 3; kh++)
#pragma unroll
            for (int kw = 0; kw < 3; kw++) {
                unsigned long long m = msk[(hy + kh) * 10 + wx + kw];
                const float* wt0 = w_s + (kh * 3 + kw) * 32 + g * 8;
                while (m) {
                    int ci = __ffsll((long long)m) - 1;
                    m &= m - 1;
                    const float* wp = wt0 + ci * 288;
                    ulonglong2 wa = *(const ulonglong2*)wp;
                    ulonglong2 wb = *(const ulonglong2*)(wp + 4);
                    acc2[0] = addf2(acc2[0], wa.x);
                    acc2[1] = addf2(acc2[1], wa.y);
                    acc2[2] = addf2(acc2[2], wb.x);
                    acc2[3] = addf2(acc2[3], wb.y);
                }
            }
    } else {
        // ---- dense fallback ----
        for (int i = tid; i < 6400; i += 256) in_s[i] = 0.f;
        __syncthreads();
        for (int i = tid; i < 4096; i += 256) {
            int ci = i >> 6, r = i & 63, h = r >> 3, ww = r & 7;
            in_s[ci * 100 + (h + 1) * 10 + (ww + 1)] = xb[i];
        }
        __syncthreads();
        for (int ci = 0; ci < 64; ci++) {
            const float* ip = in_s + ci * 100 + wx;
            const float* wp = w_s + ci * 288 + g * 8;
#pragma unroll
            for (int kh = 0; kh < 3; kh++)
#pragma unroll
                for (int kw = 0; kw < 3; kw++) {
                    int tap = kh * 3 + kw;
                    float v = ip[(hy + kh) * 10 + kw];
                    unsigned long long vs = pack2(v, v);
                    ulonglong2 wa = *(const ulonglong2*)(wp + tap * 32);
                    ulonglong2 wb = *(const ulonglong2*)(wp + tap * 32 + 4);
                    acc2[0] = ffma2(vs, wa.x, acc2[0]);
                    acc2[1] = ffma2(vs, wa.y, acc2[1]);
                    acc2[2] = ffma2(vs, wb.x, acc2[2]);
                    acc2[3] = ffma2(vs, wb.y, acc2[3]);
                }
        }
    }

    float* yb = y + (mIdx * 64 + cog * 32 + g * 8) * 64 + hy * 8 + wx;
#pragma unroll
    for (int jj = 0; jj < 4; jj++) {
        float2 c = unpack2(acc2[jj]);
        yb[(2 * jj) * 64] = c.x;
        yb[(2 * jj + 1) * 64] = c.y;
    }
}

// ---------------- fc1: C[1200][256] = X[1200][4096] . W[256][4096]^T ----------
__global__ void k_fc1(const float* __restrict__ X, const float* __restrict__ W,
                      float* __restrict__ C) {
    __shared__ float As[32][33];
    __shared__ float Bs[32][65];
    int bm = blockIdx.x, bn = blockIdx.y;
    int tid = threadIdx.x;
    int tx = tid & 15, ty = tid >> 4;
    int m0 = bm * 32, n0 = bn * 64;
    float acc[2][4];
#pragma unroll
    for (int i = 0; i < 2; i++)
#pragma unroll
        for (int j = 0; j < 4; j++) acc[i][j] = 0.f;

    for (int k0 = 0; k0 < 4096; k0 += 32) {
#pragma unroll
        for (int i = 0; i < 4; i++) {
            int idx = tid + i * 256;
            int l = idx >> 5, kk = idx & 31;
            int mg = m0 + l;
            As[kk][l] = (mg < MSL) ? X[mg * 4096 + k0 + kk] : 0.f;
        }
#pragma unroll
        for (int i = 0; i < 8; i++) {
            int idx = tid + i * 256;
            int l = idx >> 5, kk = idx & 31;
            Bs[kk][l] = W[(n0 + l) * 4096 + k0 + kk];
        }
        __syncthreads();
#pragma unroll
        for (int kk = 0; kk < 32; kk++) {
            float a[2], b[4];
#pragma unroll
            for (int i = 0; i < 2; i++) a[i] = As[kk][ty * 2 + i];
#pragma unroll
            for (int j = 0; j < 4; j++) b[j] = Bs[kk][tx * 4 + j];
#pragma unroll
            for (int i = 0; i < 2; i++)
#pragma unroll
                for (int j = 0; j < 4; j++) acc[i][j] = fmaf(a[i], b[j], acc[i][j]);
        }
        __syncthreads();
    }
#pragma unroll
    for (int i = 0; i < 2; i++) {
        int mg = m0 + ty * 2 + i;
        if (mg < MSL) {
#pragma unroll
            for (int j = 0; j < 4; j++) C[mg * 256 + n0 + tx * 4 + j] = acc[i][j];
        }
    }
}

// ---------------- fc2: [1200][11] = [1200][256] . w4b[11][256]^T ----------------
__global__ void k_fc2(const float* __restrict__ x, const float* __restrict__ w,
                      float* __restrict__ y) {
    __shared__ float xs[256];
    int m = blockIdx.x;
    int tid = threadIdx.x;
    if (tid < 256) xs[tid] = x[m * 256 + tid];
    __syncthreads();
    int o = tid >> 5, lane = tid & 31;
    const float* wr = w + o * 256;
    float acc = 0.f;
#pragma unroll
    for (int i = 0; i < 8; i++) acc = fmaf(xs[lane + 32 * i], wr[lane + 32 * i], acc);
#pragma unroll
    for (int s = 16; s; s >>= 1) acc += __shfl_xor_sync(0xffffffffu, acc, s);
    if (lane == 0) y[m * 11 + o] = acc;
}

// ---------------- host ----------------
extern "C" void kernel_launch(void* const* d_in, const int* in_sizes, int n_in,
                              void* d_out, int out_size) {
    const float* s_in = (const float*)d_in[0];
    const float* w1 = (const float*)d_in[1];
    const float* w2 = (const float*)d_in[2];
    const float* w3 = (const float*)d_in[3];
    const float* w4a = (const float*)d_in[4];
    const float* w4b = (const float*)d_in[5];
    float* out = (float*)d_out;

    float *b1, *b3, *b4, *b5, *b6, *b7, *b8, *w2t, *w3t;
    cudaGetSymbolAddress((void**)&b1, g_buf1);
    cudaGetSymbolAddress((void**)&b3, g_buf3);
    cudaGetSymbolAddress((void**)&b4, g_buf4);
    cudaGetSymbolAddress((void**)&b5, g_buf5);
    cudaGetSymbolAddress((void**)&b6, g_buf6);
    cudaGetSymbolAddress((void**)&b7, g_buf7);
    cudaGetSymbolAddress((void**)&b8, g_buf8);
    cudaGetSymbolAddress((void**)&w2t, g_w2t);
    cudaGetSymbolAddress((void**)&w3t, g_w3t);

    cudaFuncSetAttribute(k_conv1f, cudaFuncAttributeMaxDynamicSharedMemorySize, 82944);
    cudaFuncSetAttribute(k_conv2, cudaFuncAttributeMaxDynamicSharedMemorySize, 79680);
    cudaFuncSetAttribute(k_conv3, cudaFuncAttributeMaxDynamicSharedMemorySize, 100352);

    // one-shot weight transposes
    k_wt2<<<72, 256>>>(w2, w2t);
    k_wt3<<<144, 256>>>(w3, w3t);

    // stage 1: fused 4x4 pool + psp -> b1 spikes (no intermediate buffer)
    k_pool4psp<<<128, 256>>>(s_in, b1);

    // stage 2: persistent fused conv1 + psp + pool + psp -> b3 spikes
    k_conv1f<<<dim3(4, 32), 256, 82944>>>(b1, w1, b3);

    // stage 3: conv2 (density-adaptive sparse) -> fused psp+pool+psp -> b5
    k_conv2<<<dim3(MSL, 2), 256, 79680>>>(b3, w2t, b4);
    k_ppp4<64, 8, 8><<<256, 256>>>(b4, b5);

    // stage 4: conv3 (density-adaptive sparse) -> psp (in-place on b6)
    k_conv3<<<dim3(MSL, 2), 256, 100352>>>(b5, w3t, b6);
    k_psp<<<64, 256>>>(b6, 16384);

    // stage 5: fc1 -> psp, fc2 -> final psp
    k_fc1<<<dim3(38, 4), 256>>>(b6, w4a, b7);
    k_psp<<<4, 256>>>(b7, 1024);

    k_fc2<<<MSL, 352>>>(b7, w4b, b8);
    k_psp_final<<<1, 64>>>(b8, out);
}

// round 17
// speedup vs baseline: 1.0577x; 1.0577x over previous
#include <cuda_runtime.h>

// ---------------- problem constants ----------------
#define T_STEPS 300
#define NB 4
#define MSL 1200            // T_STEPS * NB time-batch slices

#define A_SR 0.90483741803595952f   // exp(-1/10)
#define A_RF 0.36787944117144233f   // exp(-1)
#define C_SR 0.27182818284590452f   // e/10
#define C_RF -54.365636569180904f   // -2*theta*e
#define THETA 10.0f

// ---------------- packed f32x2 helpers (Blackwell 2xFP32) ----------------
__device__ __forceinline__ unsigned long long ffma2(unsigned long long a,
                                                    unsigned long long b,
                                                    unsigned long long c) {
    unsigned long long d;
    asm("fma.rn.f32x2 %0, %1, %2, %3;" : "=l"(d) : "l"(a), "l"(b), "l"(c));
    return d;
}
__device__ __forceinline__ unsigned long long pack2(float lo, float hi) {
    unsigned long long d;
    asm("mov.b64 %0, {%1, %2};" : "=l"(d) : "f"(lo), "f"(hi));
    return d;
}
__device__ __forceinline__ float2 unpack2(unsigned long long d) {
    float2 r;
    asm("mov.b64 {%0, %1}, %2;" : "=f"(r.x), "=f"(r.y) : "l"(d));
    return r;
}

__device__ __forceinline__ float f4c(const float4& v, int k) {
    switch (k) {
        case 0: return v.x;
        case 1: return v.y;
        case 2: return v.z;
        default: return v.w;
    }
}

// ---------------- scratch buffers (time-major [t][n][c][h][w]) ----------------
__device__ float g_buf1[2457600];   // pooled1 spikes: [1200][2][32][32]
__device__ float g_buf3[9830400];   // pooled spikes : [1200][32][16][16]
__device__ float g_buf4[19660800];  // conv2 raw     : [1200][64][16][16]
__device__ float g_buf5[4915200];   // pooled spikes : [1200][64][8][8]
__device__ float g_buf6[4915200];   // conv3 raw/spk : [1200][64][8][8]
__device__ float g_buf7[307200];    // fc1           : [1200][256]
__device__ float g_buf8[13200];     // fc2           : [1200][11]
__device__ float g_w2t[18432];      // w2 transposed [ci32][tap9][co64]
__device__ float g_w3t[36864];      // w3 transposed [ci64][tap9][co64]

// ---------------- one-shot weight transposes ----------------
__global__ void k_wt2(const float* __restrict__ w, float* __restrict__ o) {
    int i = blockIdx.x * blockDim.x + threadIdx.x;
    if (i >= 18432) return;
    int co = i & 63, tap = (i >> 6) % 9, ci = i / 576;
    o[i] = w[co * 288 + ci * 9 + tap];
}
__global__ void k_wt3(const float* __restrict__ w, float* __restrict__ o) {
    int i = blockIdx.x * blockDim.x + threadIdx.x;
    if (i >= 36864) return;
    int co = i & 63, tap = (i >> 6) % 9, ci = i / 576;
    o[i] = w[co * 576 + ci * 9 + tap];
}

// ---------------- fused 4x4 pool + psp, 16 threads per pooled neuron ----------
// Each of the 16 lanes owns one input pixel of the 4x4 window: one contiguous
// float4-over-t load per 4-step chunk. Pool sum via 4-level bfly shfl (sums of
// binary spikes -> exact). IIR computed redundantly; lane 0 writes the spike.
__global__ void k_pool4psp(const float* __restrict__ s_in, float* __restrict__ y) {
    int j = blockIdx.x * blockDim.x + threadIdx.x;
    if (j >= 131072) return;
    int neuron = j >> 4, lane = j & 15;
    int q = lane >> 2, dj = lane & 3;
    int w = neuron & 31, h = (neuron >> 5) & 31, c = (neuron >> 10) & 1, n = neuron >> 11;
    const float* src = s_in + ((((n * 2 + c) * 128 + h * 4 + q) * 128) + w * 4 + dj) * 300;

    float4 cur = *(const float4*)src, nxt;
    float gp = 0.f, hp = 0.f, gr = 0.f, hr = 0.f;

    for (int ch = 0; ch < 75; ch++) {
        if (ch < 74) nxt = *(const float4*)(src + 4 * (ch + 1));
#pragma unroll
        for (int k = 0; k < 4; k++) {
            int t = 4 * ch + k;
            float v = f4c(cur, k);
            v += __shfl_xor_sync(0xffffffffu, v, 1);
            v += __shfl_xor_sync(0xffffffffu, v, 2);
            v += __shfl_xor_sync(0xffffffffu, v, 4);
            v += __shfl_xor_sync(0xffffffffu, v, 8);
            float pv = 11.0f * v;
            hp = A_SR * (hp + gp);
            gp = fmaf(A_SR, gp, pv);
            hr = A_RF * (hr + gr);
            gr = A_RF * gr;
            float u = fmaf(C_SR, hp, C_RF * hr);
            float s = (u >= THETA) ? 1.0f : 0.0f;
            gr += s;
            if (lane == 0) y[t * 8192 + neuron] = s;
        }
        cur = nxt;
    }
}

// ---------------- psp + spike, in-place, depth-4 prefetch ring ----------------
__global__ void k_psp(float* __restrict__ x, int nn) {
    int j = blockIdx.x * blockDim.x + threadIdx.x;
    if (j >= nn) return;
    float buf[4];
#pragma unroll
    for (int t = 0; t < 4; t++) buf[t] = x[t * nn + j];
    float gp = 0.f, hp = 0.f, gr = 0.f, hr = 0.f;
    for (int t = 0; t < T_STEPS; t++) {
        int slot = t & 3;
        float v = buf[slot];
        if (t + 4 < T_STEPS) buf[slot] = x[(t + 4) * nn + j];
        hp = A_SR * (hp + gp);
        gp = fmaf(A_SR, gp, v);
        hr = A_RF * (hr + gr);
        gr = A_RF * gr;
        float u = fmaf(C_SR, hp, C_RF * hr);
        float s = (u >= THETA) ? 1.0f : 0.0f;
        x[t * nn + j] = s;
        gr += s;
    }
}

// final psp: reads [t][44], depth-4 prefetch, writes d_out in (N,11,T) layout
__global__ void k_psp_final(const float* __restrict__ x, float* __restrict__ out) {
    int j = threadIdx.x;
    if (j >= 44) return;
    float buf[4];
#pragma unroll
    for (int t = 0; t < 4; t++) buf[t] = x[t * 44 + j];
    float gp = 0.f, hp = 0.f, gr = 0.f, hr = 0.f;
    for (int t = 0; t < T_STEPS; t++) {
        int slot = t & 3;
        float v = buf[slot];
        if (t + 4 < T_STEPS) buf[slot] = x[(t + 4) * 44 + j];
        hp = A_SR * (hp + gp);
        gp = fmaf(A_SR, gp, v);
        hr = A_RF * (hr + gr);
        gr = A_RF * gr;
        float u = fmaf(C_SR, hp, C_RF * hr);
        float s = (u >= THETA) ? 1.0f : 0.0f;
        out[j * T_STEPS + t] = s;
        gr += s;
    }
}

// ---------------- persistent fused conv1 + psp + 2x2 pool + psp ----------------
#define C1_SLICE 1296               // 36*36
#define C1_TBUF (2 * C1_SLICE)      // one t: 2 ci planes
__global__ void __launch_bounds__(256, 1)
k_conv1f(const float* __restrict__ x, const float* __restrict__ w,
         float* __restrict__ y) {
    extern __shared__ float sm[];   // [buf2][tt4][ci2][36][36]
    int n = blockIdx.x, co = blockIdx.y;
    int tid = threadIdx.x;
    int pw = tid & 15, ph = tid >> 4;

    for (int i = tid; i < 2 * 4 * C1_TBUF; i += 256) sm[i] = 0.f;

    float wr[50];
#pragma unroll
    for (int i = 0; i < 50; i++) wr[i] = w[co * 50 + i];

    __syncthreads();
    const float* xb = x + n * 2048;
    const int TSTR = 8192;          // floats per t in b1: 4n * 2048

#pragma unroll
    for (int tt = 0; tt < 4; tt++) {
        const float* xp = xb + tt * TSTR;
#pragma unroll
        for (int k = 0; k < 2; k++) {
            int idx = tid + k * 256;
            float4 f = ((const float4*)xp)[idx];
            int lin = idx * 4;
            int ci = lin >> 10, r = lin & 1023, h = r >> 5, ww = r & 31;
            float* dst = sm + tt * C1_TBUF + ci * C1_SLICE + (h + 2) * 36 + (ww + 2);
            dst[0] = f.x; dst[1] = f.y; dst[2] = f.z; dst[3] = f.w;
        }
    }
    __syncthreads();

    float gp[4] = {0, 0, 0, 0}, hp[4] = {0, 0, 0, 0};
    float gr[4] = {0, 0, 0, 0}, hr[4] = {0, 0, 0, 0};
    float gpp = 0.f, hpp = 0.f, grp = 0.f, hrp = 0.f;

    for (int c = 0; c < 75; c++) {
        int cb = c & 1;
        float* cbuf = sm + cb * 4 * C1_TBUF;
        if (c < 74) {
            float* nbuf = sm + (cb ^ 1) * 4 * C1_TBUF;
#pragma unroll
            for (int tt = 0; tt < 4; tt++) {
                const float* xp = xb + (4 * (c + 1) + tt) * TSTR;
#pragma unroll
                for (int k = 0; k < 2; k++) {
                    int idx = tid + k * 256;
                    float4 f = ((const float4*)xp)[idx];
                    int lin = idx * 4;
                    int ci = lin >> 10, r = lin & 1023, h = r >> 5, ww = r & 31;
                    float* dst = nbuf + tt * C1_TBUF + ci * C1_SLICE + (h + 2) * 36 + (ww + 2);
                    dst[0] = f.x; dst[1] = f.y; dst[2] = f.z; dst[3] = f.w;
                }
            }
        }
#pragma unroll
        for (int tt = 0; tt < 4; tt++) {
            int t = 4 * c + tt;
            const float* tb = cbuf + tt * C1_TBUF;
            unsigned long long a0 = 0ull, a1 = 0ull;
#pragma unroll
            for (int ci = 0; ci < 2; ci++) {
                const float* pb = tb + ci * C1_SLICE;
                float p[6][6];
#pragma unroll
                for (int r = 0; r < 6; r++) {
#pragma unroll
                    for (int cpair = 0; cpair < 3; cpair++) {
                        float2 v = *(const float2*)(pb + (2 * ph + r) * 36 + 2 * pw + 2 * cpair);
                        p[r][2 * cpair] = v.x;
                        p[r][2 * cpair + 1] = v.y;
                    }
                }
#pragma unroll
                for (int kh = 0; kh < 5; kh++)
#pragma unroll
                    for (int kw = 0; kw < 5; kw++) {
                        float wv = wr[ci * 25 + kh * 5 + kw];
                        unsigned long long ws = pack2(wv, wv);
                        a0 = ffma2(pack2(p[kh][kw], p[kh][kw + 1]), ws, a0);
                        a1 = ffma2(pack2(p[kh + 1][kw], p[kh + 1][kw + 1]), ws, a1);
                    }
            }
            float2 f0 = unpack2(a0), f1 = unpack2(a1);
            float av[4] = {f0.x, f0.y, f1.x, f1.y};
            float psum = 0.f;
#pragma unroll
            for (int k = 0; k < 4; k++) {
                hp[k] = A_SR * (hp[k] + gp[k]);
                gp[k] = fmaf(A_SR, gp[k], av[k]);
                hr[k] = A_RF * (hr[k] + gr[k]);
                gr[k] = A_RF * gr[k];
                float u = fmaf(C_SR, hp[k], C_RF * hr[k]);
                float s = (u >= THETA) ? 1.0f : 0.0f;
                gr[k] += s;
                psum += s;
            }
            float pv = 11.0f * psum;
            hpp = A_SR * (hpp + gpp);
            gpp = fmaf(A_SR, gpp, pv);
            hrp = A_RF * (hrp + grp);
            grp = A_RF * grp;
            float u = fmaf(C_SR, hpp, C_RF * hrp);
            float s = (u >= THETA) ? 1.0f : 0.0f;
            grp += s;
            y[t * 32768 + ((n * 32 + co) * 16 + ph) * 16 + pw] = s;
        }
        __syncthreads();
    }
}

// ---------------- fused psp -> 2x2 pool -> psp, 4 threads per pooled neuron ----
template <int C, int HO, int WO>
__global__ void k_ppp4(const float* __restrict__ x, float* __restrict__ y) {
    const int NN = 4 * C * HO * WO;
    const int WI = 2 * WO;
    const int STRIDE = 4 * C * (2 * HO) * WI;
    int j = blockIdx.x * blockDim.x + threadIdx.x;
    if (j >= 4 * NN) return;
    int neuron = j >> 2, q = j & 3;
    int wo = neuron % WO, ho = (neuron / WO) % HO;
    int c = (neuron / (WO * HO)) % C, n = neuron / (WO * HO * C);
    const float* src = x + (((n * C + c) * (2 * HO) + 2 * ho + (q >> 1)) * WI) +
                       2 * wo + (q & 1);

    float buf[4];
#pragma unroll
    for (int t = 0; t < 4; t++) buf[t] = src[t * STRIDE];

    float gp = 0.f, hp = 0.f, gr = 0.f, hr = 0.f;
    float gpp = 0.f, hpp = 0.f, grp = 0.f, hrp = 0.f;

    for (int t = 0; t < T_STEPS; t++) {
        int slot = t & 3;
        float v = buf[slot];
        if (t + 4 < T_STEPS) buf[slot] = src[(t + 4) * STRIDE];
        hp = A_SR * (hp + gp);
        gp = fmaf(A_SR, gp, v);
        hr = A_RF * (hr + gr);
        gr = A_RF * gr;
        float u = fmaf(C_SR, hp, C_RF * hr);
        float s = (u >= THETA) ? 1.0f : 0.0f;
        gr += s;
        s += __shfl_xor_sync(0xffffffffu, s, 1);
        s += __shfl_xor_sync(0xffffffffu, s, 2);
        float pv = 11.0f * s;
        hpp = A_SR * (hpp + gpp);
        gpp = fmaf(A_SR, gpp, pv);
        hrp = A_RF * (hrp + grp);
        grp = A_RF * grp;
        float up = fmaf(C_SR, hpp, C_RF * hrp);
        float sp = (up >= THETA) ? 1.0f : 0.0f;
        grp += sp;
        if (q == 0) y[t * NN + neuron] = sp;
    }
}

// ---------------- conv2: 3x3, 32->64, 16x16, pad 1  (f32x2, g-in-warp) --------
__global__ void k_conv2(const float* __restrict__ x, const float* __restrict__ wt,
                        float* __restrict__ y) {
    extern __shared__ float sm[];
    float* in_s = sm;           // 32*18*18 = 10368
    float* w_s = sm + 10368;    // [ci][tap][32co] = 9216
    int m = blockIdx.x;
    int cog = blockIdx.y;
    int tid = threadIdx.x;
    for (int i = tid; i < 10368; i += 256) in_s[i] = 0.f;
    __syncthreads();
    const float* xb = x + m * 8192;
    for (int i = tid; i < 8192; i += 256) {
        int ci = i >> 8, r = i & 255, h = r >> 4, ww = r & 15;
        in_s[ci * 324 + (h + 1) * 18 + (ww + 1)] = xb[i];
    }
    for (int i = tid; i < 9216; i += 256)
        w_s[i] = wt[(i >> 5) * 64 + cog * 32 + (i & 31)];
    __syncthreads();

    int wx = tid & 15, g = (tid >> 4) & 3, ty = tid >> 6;
    unsigned long long acc2[4][4];
#pragma unroll
    for (int p = 0; p < 4; p++)
#pragma unroll
        for (int jj = 0; jj < 4; jj++) acc2[p][jj] = 0ull;

    for (int ci = 0; ci < 32; ci++) {
        const float* ip = in_s + ci * 324 + wx;
        const float* wp = w_s + ci * 288 + g * 8;
#pragma unroll
        for (int kh = 0; kh < 3; kh++)
#pragma unroll
            for (int kw = 0; kw < 3; kw++) {
                int tap = kh * 3 + kw;
                ulonglong2 wa = *(const ulonglong2*)(wp + tap * 32);
                ulonglong2 wb = *(const ulonglong2*)(wp + tap * 32 + 4);
                unsigned long long wv2[4] = {wa.x, wa.y, wb.x, wb.y};
#pragma unroll
                for (int p = 0; p < 4; p++) {
                    float v = ip[(ty + 4 * p + kh) * 18 + kw];
                    unsigned long long vs = pack2(v, v);
#pragma unroll
                    for (int jj = 0; jj < 4; jj++)
                        acc2[p][jj] = ffma2(vs, wv2[jj], acc2[p][jj]);
                }
            }
    }

    float* yb = y + (m * 64 + cog * 32 + g * 8) * 256;
#pragma unroll
    for (int p = 0; p < 4; p++) {
        int h = ty + 4 * p;
#pragma unroll
        for (int jj = 0; jj < 4; jj++) {
            float2 c = unpack2(acc2[p][jj]);
            yb[(2 * jj) * 256 + h * 16 + wx] = c.x;
            yb[(2 * jj + 1) * 256 + h * 16 + wx] = c.y;
        }
    }
}

// ---------------- conv3: 3x3, 64->64, 8x8, pad 1  (f32x2, g-in-warp) ----------
__global__ void k_conv3(const float* __restrict__ x, const float* __restrict__ wt,
                        float* __restrict__ y) {
    extern __shared__ float sm[];
    float* in_s = sm;          // 64*10*10 = 6400
    float* w_s = sm + 6400;    // [ci64][tap][32co] = 18432
    int m = blockIdx.x;
    int cog = blockIdx.y;
    int tid = threadIdx.x;
    for (int i = tid; i < 6400; i += 256) in_s[i] = 0.f;
    __syncthreads();
    const float* xb = x + m * 4096;
    for (int i = tid; i < 4096; i += 256) {
        int ci = i >> 6, r = i & 63, h = r >> 3, ww = r & 7;
        in_s[ci * 100 + (h + 1) * 10 + (ww + 1)] = xb[i];
    }
    for (int i = tid; i < 18432; i += 256)
        w_s[i] = wt[(i >> 5) * 64 + cog * 32 + (i & 31)];
    __syncthreads();

    int wx = tid & 7, g = (tid >> 3) & 3, hy = tid >> 5;
    unsigned long long acc2[4] = {0ull, 0ull, 0ull, 0ull};

    for (int ci = 0; ci < 64; ci++) {
        const float* ip = in_s + ci * 100 + wx;
        const float* wp = w_s + ci * 288 + g * 8;
#pragma unroll
        for (int kh = 0; kh < 3; kh++)
#pragma unroll
            for (int kw = 0; kw < 3; kw++) {
                int tap = kh * 3 + kw;
                float v = ip[(hy + kh) * 10 + kw];
                unsigned long long vs = pack2(v, v);
                ulonglong2 wa = *(const ulonglong2*)(wp + tap * 32);
                ulonglong2 wb = *(const ulonglong2*)(wp + tap * 32 + 4);
                acc2[0] = ffma2(vs, wa.x, acc2[0]);
                acc2[1] = ffma2(vs, wa.y, acc2[1]);
                acc2[2] = ffma2(vs, wb.x, acc2[2]);
                acc2[3] = ffma2(vs, wb.y, acc2[3]);
            }
    }

    float* yb = y + (m * 64 + cog * 32 + g * 8) * 64 + hy * 8 + wx;
#pragma unroll
    for (int jj = 0; jj < 4; jj++) {
        float2 c = unpack2(acc2[jj]);
        yb[(2 * jj) * 64] = c.x;
        yb[(2 * jj + 1) * 64] = c.y;
    }
}

// ---------------- fc1: C[1200][256] = X[1200][4096] . W[256][4096]^T ----------
// f32x2 accumulators; Bs rows padded to 66 floats so LDS.64 of co pairs is
// 8B-aligned for every kk row.
__global__ void k_fc1(const float* __restrict__ X, const float* __restrict__ W,
                      float* __restrict__ C) {
    __shared__ float As[32][33];
    __shared__ float Bs[32][66];
    int bm = blockIdx.x, bn = blockIdx.y;
    int tid = threadIdx.x;
    int tx = tid & 15, ty = tid >> 4;
    int m0 = bm * 32, n0 = bn * 64;
    unsigned long long acc2[2][2] = {{0ull, 0ull}, {0ull, 0ull}};

    for (int k0 = 0; k0 < 4096; k0 += 32) {
#pragma unroll
        for (int i = 0; i < 4; i++) {
            int idx = tid + i * 256;
            int l = idx >> 5, kk = idx & 31;
            int mg = m0 + l;
            As[kk][l] = (mg < MSL) ? X[mg * 4096 + k0 + kk] : 0.f;
        }
#pragma unroll
        for (int i = 0; i < 8; i++) {
            int idx = tid + i * 256;
            int l = idx >> 5, kk = idx & 31;
            Bs[kk][l] = W[(n0 + l) * 4096 + k0 + kk];
        }
        __syncthreads();
#pragma unroll
        for (int kk = 0; kk < 32; kk++) {
            float a0 = As[kk][ty * 2], a1 = As[kk][ty * 2 + 1];
            unsigned long long av0 = pack2(a0, a0), av1 = pack2(a1, a1);
            unsigned long long b0 = *(const unsigned long long*)&Bs[kk][tx * 4];
            unsigned long long b1 = *(const unsigned long long*)&Bs[kk][tx * 4 + 2];
            acc2[0][0] = ffma2(av0, b0, acc2[0][0]);
            acc2[0][1] = ffma2(av0, b1, acc2[0][1]);
            acc2[1][0] = ffma2(av1, b0, acc2[1][0]);
            acc2[1][1] = ffma2(av1, b1, acc2[1][1]);
        }
        __syncthreads();
    }
#pragma unroll
    for (int i = 0; i < 2; i++) {
        int mg = m0 + ty * 2 + i;
        if (mg < MSL) {
            float2 c0 = unpack2(acc2[i][0]), c1 = unpack2(acc2[i][1]);
            float* cp = C + mg * 256 + n0 + tx * 4;
            cp[0] = c0.x; cp[1] = c0.y; cp[2] = c1.x; cp[3] = c1.y;
        }
    }
}

// ---------------- fc2: [1200][11] = [1200][256] . w4b[11][256]^T ----------------
__global__ void k_fc2(const float* __restrict__ x, const float* __restrict__ w,
                      float* __restrict__ y) {
    __shared__ float xs[256];
    int m = blockIdx.x;
    int tid = threadIdx.x;
    if (tid < 256) xs[tid] = x[m * 256 + tid];
    __syncthreads();
    int o = tid >> 5, lane = tid & 31;
    const float* wr = w + o * 256;
    float acc = 0.f;
#pragma unroll
    for (int i = 0; i < 8; i++) acc = fmaf(xs[lane + 32 * i], wr[lane + 32 * i], acc);
#pragma unroll
    for (int s = 16; s; s >>= 1) acc += __shfl_xor_sync(0xffffffffu, acc, s);
    if (lane == 0) y[m * 11 + o] = acc;
}

// ---------------- host ----------------
extern "C" void kernel_launch(void* const* d_in, const int* in_sizes, int n_in,
                              void* d_out, int out_size) {
    const float* s_in = (const float*)d_in[0];
    const float* w1 = (const float*)d_in[1];
    const float* w2 = (const float*)d_in[2];
    const float* w3 = (const float*)d_in[3];
    const float* w4a = (const float*)d_in[4];
    const float* w4b = (const float*)d_in[5];
    float* out = (float*)d_out;

    float *b1, *b3, *b4, *b5, *b6, *b7, *b8, *w2t, *w3t;
    cudaGetSymbolAddress((void**)&b1, g_buf1);
    cudaGetSymbolAddress((void**)&b3, g_buf3);
    cudaGetSymbolAddress((void**)&b4, g_buf4);
    cudaGetSymbolAddress((void**)&b5, g_buf5);
    cudaGetSymbolAddress((void**)&b6, g_buf6);
    cudaGetSymbolAddress((void**)&b7, g_buf7);
    cudaGetSymbolAddress((void**)&b8, g_buf8);
    cudaGetSymbolAddress((void**)&w2t, g_w2t);
    cudaGetSymbolAddress((void**)&w3t, g_w3t);

    cudaFuncSetAttribute(k_conv1f, cudaFuncAttributeMaxDynamicSharedMemorySize, 82944);
    cudaFuncSetAttribute(k_conv2, cudaFuncAttributeMaxDynamicSharedMemorySize, 78336);
    cudaFuncSetAttribute(k_conv3, cudaFuncAttributeMaxDynamicSharedMemorySize, 99328);

    // one-shot weight transposes
    k_wt2<<<72, 256>>>(w2, w2t);
    k_wt3<<<144, 256>>>(w3, w3t);

    // stage 1: fused 4x4 pool + psp (16 threads/neuron) -> b1 spikes
    k_pool4psp<<<512, 256>>>(s_in, b1);

    // stage 2: persistent fused conv1 + psp + pool + psp -> b3 spikes
    k_conv1f<<<dim3(4, 32), 256, 82944>>>(b1, w1, b3);

    // stage 3: conv2 -> fused psp+pool+psp (4 thr/neuron) -> b5 spikes
    k_conv2<<<dim3(MSL, 2), 256, 78336>>>(b3, w2t, b4);
    k_ppp4<64, 8, 8><<<512, 128>>>(b4, b5);

    // stage 4: conv3 -> psp (in-place spikes on b6)
    k_conv3<<<dim3(MSL, 2), 256, 99328>>>(b5, w3t, b6);
    k_psp<<<128, 128>>>(b6, 16384);

    // stage 5: fc1 -> psp, fc2 -> final psp
    k_fc1<<<dim3(38, 4), 256>>>(b6, w4a, b7);
    k_psp<<<8, 128>>>(b7, 1024);

    k_fc2<<<MSL, 352>>>(b7, w4b, b8);
    k_psp_final<<<1, 64>>>(b8, out);
}